// round 1
// baseline (speedup 1.0000x reference)
#include <cuda_runtime.h>
#include <cuda_bf16.h>

#define TX 32
#define TY 32
#define NTHREADS 256

// Cross-block loss accumulator (double for deterministic-enough precision).
__device__ double g_acc;

__global__ void zero_acc_kernel() { g_acc = 0.0; }

__global__ void finalize_kernel(float* out) {
    const double cnt = 256.0 * 254.0 * 254.0;
    out[0] = (float)(g_acc / cnt);
}

__global__ __launch_bounds__(NTHREADS) void pde_loss_kernel(
    const float* __restrict__ pred,   // [256,256,256]
    const float* __restrict__ rhs,    // [256,254,254]
    const float* __restrict__ kL,     // [256,3,3]
    const float* __restrict__ kD,     // [256,3,3]
    const float* __restrict__ RR,     // [256,256,256] (broadcast of r along rows)
    const float* __restrict__ ZZ,     // [256,256,256]
    const float* __restrict__ G)      // [3,3]
{
    const int H = 256, W = 256, OH = 254, OW = 254;
    const int b   = blockIdx.z;
    const int tx0 = blockIdx.x * TX;
    const int ty0 = blockIdx.y * TY;

    __shared__ float sp[TY + 4][TX + 4 + 1];   // pred tile + halo(2): 36 x 37
    __shared__ float sg[TY + 2][TX + 2 + 1];   // GS tile + halo(1):   34 x 35
    __shared__ float rinv[TX + 2];             // 1/r per GS column
    __shared__ float skL[9], skD[9], sG[9];
    __shared__ float warp_part[NTHREADS / 32];

    const int tid = threadIdx.x;
    const size_t bHW = (size_t)b * H * W;

    if (tid < 9) {
        skL[tid] = kL[b * 9 + tid];
        skD[tid] = kD[b * 9 + tid];
        sG[tid]  = G[tid];
    }
    if (tid < TX + 2) {
        // GS column q = tx0 - 1 + tid; divides by RR[b, 1+i, 1+q] == RR[b, 1, 1+q]
        int q = tx0 - 1 + tid;
        float r = (q >= 0 && q < OW) ? RR[bHW + W + (q + 1)] : 1.0f;
        rinv[tid] = 1.0f / r;
    }

    // Load pred tile with radius-2 halo, zero-filled out of range.
    const float* pb = pred + bHW;
    #pragma unroll
    for (int idx = tid; idx < (TY + 4) * (TX + 4); idx += NTHREADS) {
        int sy = idx / (TX + 4);
        int sx = idx % (TX + 4);
        int gy = ty0 - 1 + sy;
        int gx = tx0 - 1 + sx;
        float v = 0.0f;
        if (gy >= 0 && gy < H && gx >= 0 && gx < W) v = pb[gy * W + gx];
        sp[sy][sx] = v;
    }
    __syncthreads();

    // Grid-spacing scale (RR/ZZ are broadcast meshgrids; 4 scalar reads).
    float hr = RR[bHW + W + 2]     - RR[bHW + W + 1];
    float hz = ZZ[bHW + 2 * W + 1] - ZZ[bHW + W + 1];
    float hr2 = hr * hr, hz2 = hz * hz;
    float scale = (-2.0f * (hr2 + hz2)) / (hr2 * hz2);

    // Stage 1: GS_ope on the (TY+2)x(TX+2) halo tile (zero outside [0,254)^2
    // which implements the SAME zero padding of the Gaussian conv).
    for (int idx = tid; idx < (TY + 2) * (TX + 2); idx += NTHREADS) {
        int sy = idx / (TX + 2);
        int sx = idx % (TX + 2);
        int p = ty0 - 1 + sy;
        int q = tx0 - 1 + sx;
        float g = 0.0f;
        if (p >= 0 && p < OH && q >= 0 && q < OW) {
            float sl = 0.0f, sd = 0.0f;
            #pragma unroll
            for (int u = 0; u < 3; u++) {
                #pragma unroll
                for (int v = 0; v < 3; v++) {
                    float x = sp[sy + u][sx + v];
                    sl = fmaf(x, skL[3 * u + v], sl);
                    sd = fmaf(x, skD[3 * u + v], sd);
                }
            }
            // Lpsi = sl; Dpsi_dr = -sd / r; lhs = sl + sd/r; GS = lhs * scale
            g = scale * fmaf(sd, rinv[sx], sl);
        }
        sg[sy][sx] = g;
    }
    __syncthreads();

    // Stage 2: Gaussian smooth + squared error vs rhs, block-local reduce.
    float acc = 0.0f;
    const float* rb = rhs + (size_t)b * OH * OW;
    for (int idx = tid; idx < TY * TX; idx += NTHREADS) {
        int oyl = idx / TX;
        int oxl = idx % TX;
        int oy = ty0 + oyl;
        int ox = tx0 + oxl;
        if (oy < OH && ox < OW) {
            float s = 0.0f;
            #pragma unroll
            for (int dy = 0; dy < 3; dy++) {
                #pragma unroll
                for (int dx = 0; dx < 3; dx++) {
                    s = fmaf(sg[oyl + dy][oxl + dx], sG[3 * dy + dx], s);
                }
            }
            float d = s - rb[oy * OW + ox];
            acc = fmaf(d, d, acc);
        }
    }

    // Warp shuffle reduce, then one double atomic per block.
    #pragma unroll
    for (int off = 16; off > 0; off >>= 1)
        acc += __shfl_xor_sync(0xFFFFFFFFu, acc, off);
    if ((tid & 31) == 0) warp_part[tid >> 5] = acc;
    __syncthreads();
    if (tid == 0) {
        double s = 0.0;
        #pragma unroll
        for (int w = 0; w < NTHREADS / 32; w++) s += (double)warp_part[w];
        atomicAdd(&g_acc, s);
    }
}

extern "C" void kernel_launch(void* const* d_in, const int* in_sizes, int n_in,
                              void* d_out, int out_size) {
    const float* pred = (const float*)d_in[0];
    const float* rhs  = (const float*)d_in[1];
    const float* kL   = (const float*)d_in[2];
    const float* kD   = (const float*)d_in[3];
    const float* RR   = (const float*)d_in[4];
    const float* ZZ   = (const float*)d_in[5];
    const float* G    = (const float*)d_in[6];
    float* out = (float*)d_out;

    zero_acc_kernel<<<1, 1>>>();
    dim3 grid((254 + TX - 1) / TX, (254 + TY - 1) / TY, 256);  // 8 x 8 x 256
    pde_loss_kernel<<<grid, NTHREADS>>>(pred, rhs, kL, kD, RR, ZZ, G);
    finalize_kernel<<<1, 1>>>(out);
}